// round 2
// baseline (speedup 1.0000x reference)
#include <cuda_runtime.h>
#include <math.h>

// Problem shape (fixed)
#define NB  4
#define NS  2048
#define ND  1024
#define NH  16
#define NHD 64
#define NM  (NB * NS)   // 8192 rows

// Scratch (device globals: allocation-free)
__device__ float g_Qp[(size_t)NB * NS * ND];
__device__ float g_Kp[(size_t)NB * NS * ND];
__device__ float g_Vp[(size_t)NB * NS * ND];
__device__ float g_mg[(size_t)NB * NS * ND];

// ----------------------------------------------------------------------------
// C[M,N] = A[M,K] @ W[N,K]^T + bias[N]   (M=8192, N=K=1024 fixed)
// BM=BN=64, BK=16, 256 threads, 4x4 micro-tile.
// srcsel: 0 -> Aext, 1 -> g_mg.   dstsel: 0->g_Qp 1->g_Kp 2->g_Vp 3->Cext
// ----------------------------------------------------------------------------
__global__ __launch_bounds__(256, 2) void gemm_nt_bias(
    const float* __restrict__ Aext,
    const float* __restrict__ W,
    const float* __restrict__ bias,
    float* __restrict__ Cext,
    int srcsel, int dstsel)
{
    const int K = ND, N = ND;
    __shared__ float As[16][68];   // [k][m], padded
    __shared__ float Ws[16][68];   // [k][n], padded

    const float* A = (srcsel == 0) ? Aext : g_mg;
    float* C = (dstsel == 0) ? g_Qp
             : (dstsel == 1) ? g_Kp
             : (dstsel == 2) ? g_Vp
             : Cext;

    const int t  = threadIdx.x;
    const int tx = t & 15;
    const int ty = t >> 4;
    const int m0 = blockIdx.y * 64;
    const int n0 = blockIdx.x * 64;

    const int lr = t >> 2;         // tile row 0..63
    const int lc = (t & 3) << 2;   // k offset {0,4,8,12}

    float acc[4][4] = {};

    const float* aLd = A + (size_t)(m0 + lr) * K + lc;
    const float* wLd = W + (size_t)(n0 + lr) * K + lc;

    for (int k0 = 0; k0 < K; k0 += 16) {
        float4 a4 = *(const float4*)(aLd + k0);
        float4 w4 = *(const float4*)(wLd + k0);
        As[lc + 0][lr] = a4.x; As[lc + 1][lr] = a4.y;
        As[lc + 2][lr] = a4.z; As[lc + 3][lr] = a4.w;
        Ws[lc + 0][lr] = w4.x; Ws[lc + 1][lr] = w4.y;
        Ws[lc + 2][lr] = w4.z; Ws[lc + 3][lr] = w4.w;
        __syncthreads();

        #pragma unroll
        for (int k = 0; k < 16; k++) {
            float4 av = *(const float4*)&As[k][ty * 4];
            float4 wv = *(const float4*)&Ws[k][tx * 4];
            float a[4] = {av.x, av.y, av.z, av.w};
            float w[4] = {wv.x, wv.y, wv.z, wv.w};
            #pragma unroll
            for (int i = 0; i < 4; i++)
                #pragma unroll
                for (int j = 0; j < 4; j++)
                    acc[i][j] += a[i] * w[j];
        }
        __syncthreads();
    }

    float4 b4 = *(const float4*)&bias[n0 + tx * 4];
    #pragma unroll
    for (int i = 0; i < 4; i++) {
        float4 o;
        o.x = acc[i][0] + b4.x;
        o.y = acc[i][1] + b4.y;
        o.z = acc[i][2] + b4.z;
        o.w = acc[i][3] + b4.w;
        *(float4*)&C[(size_t)(m0 + ty * 4 + i) * N + n0 + tx * 4] = o;
    }
}

// ----------------------------------------------------------------------------
// Flash-style attention. Grid: (B*H, S/128), 128 threads (one per query row).
// Reads g_Qp/g_Kp/g_Vp; writes ctx [B,H,S,HD] and g_mg [B,S,D] (merged).
// ----------------------------------------------------------------------------
__global__ __launch_bounds__(128) void attn_kernel(float* __restrict__ ctx_out)
{
    __shared__ float Ksm[64 * NHD];
    __shared__ float Vsm[64 * NHD];

    const int bh = blockIdx.x;
    const int b  = bh >> 4;       // / NH
    const int h  = bh & 15;       // % NH
    const int t  = threadIdx.x;
    const int qr = blockIdx.y * 128 + t;

    float q[NHD], acc[NHD];
    {
        const float4* qp = (const float4*)&g_Qp[((size_t)b * NS + qr) * ND + h * NHD];
        #pragma unroll
        for (int i = 0; i < 16; i++) {
            float4 v4 = qp[i];
            q[4 * i + 0] = v4.x; q[4 * i + 1] = v4.y;
            q[4 * i + 2] = v4.z; q[4 * i + 3] = v4.w;
        }
    }
    #pragma unroll
    for (int d = 0; d < NHD; d++) acc[d] = 0.0f;

    float m = -1e30f;
    float l = 0.0f;

    for (int kt = 0; kt < NS / 64; kt++) {
        // Cooperative load of K/V tile (64 keys x 64 dims), fully coalesced.
        #pragma unroll
        for (int i = 0; i < 8; i++) {
            int f   = i * 128 + t;            // float4 index in tile (0..1023)
            int row = f >> 4;
            int c4  = f & 15;
            size_t g = ((size_t)b * NS + (size_t)kt * 64 + row) * ND + h * NHD + c4 * 4;
            ((float4*)Ksm)[f] = *(const float4*)&g_Kp[g];
            ((float4*)Vsm)[f] = *(const float4*)&g_Vp[g];
        }
        __syncthreads();

        #pragma unroll 4
        for (int j = 0; j < 64; j++) {
            // score = (q . K[j]) / sqrt(64); K row broadcast via smem (no conflicts)
            const float4* kr = (const float4*)&Ksm[j * NHD];
            float s0 = 0.f, s1 = 0.f, s2 = 0.f, s3 = 0.f;
            #pragma unroll
            for (int d4 = 0; d4 < 16; d4++) {
                float4 kv = kr[d4];
                s0 += q[4 * d4 + 0] * kv.x;
                s1 += q[4 * d4 + 1] * kv.y;
                s2 += q[4 * d4 + 2] * kv.z;
                s3 += q[4 * d4 + 3] * kv.w;
            }
            float sj = ((s0 + s1) + (s2 + s3)) * 0.125f;

            // Online softmax: rescale only when the running max changes (rare).
            if (sj > m) {
                float corr = __expf(m - sj);
                l *= corr;
                #pragma unroll
                for (int d = 0; d < NHD; d++) acc[d] *= corr;
                m = sj;
            }
            float w = __expf(sj - m);
            l += w;

            const float4* vr = (const float4*)&Vsm[j * NHD];
            #pragma unroll
            for (int d4 = 0; d4 < 16; d4++) {
                float4 vv = vr[d4];
                acc[4 * d4 + 0] += w * vv.x;
                acc[4 * d4 + 1] += w * vv.y;
                acc[4 * d4 + 2] += w * vv.z;
                acc[4 * d4 + 3] += w * vv.w;
            }
        }
        __syncthreads();
    }

    const float inv = 1.0f / l;
    float* cp = &ctx_out[(((size_t)b * NH + h) * NS + qr) * NHD];
    float* mp = &g_mg[((size_t)b * NS + qr) * ND + h * NHD];
    #pragma unroll
    for (int d4 = 0; d4 < 16; d4++) {
        float4 o;
        o.x = acc[4 * d4 + 0] * inv;
        o.y = acc[4 * d4 + 1] * inv;
        o.z = acc[4 * d4 + 2] * inv;
        o.w = acc[4 * d4 + 3] * inv;
        *(float4*)&cp[d4 * 4] = o;
        *(float4*)&mp[d4 * 4] = o;
    }
}

// ----------------------------------------------------------------------------
extern "C" void kernel_launch(void* const* d_in, const int* in_sizes, int n_in,
                              void* d_out, int out_size)
{
    (void)in_sizes; (void)n_in; (void)out_size;
    const float* q    = (const float*)d_in[0];
    const float* k    = (const float*)d_in[1];
    const float* v    = (const float*)d_in[2];
    const float* wq_w = (const float*)d_in[3];
    const float* wq_b = (const float*)d_in[4];
    const float* wk_w = (const float*)d_in[5];
    const float* wk_b = (const float*)d_in[6];
    const float* wv_w = (const float*)d_in[7];
    const float* wv_b = (const float*)d_in[8];
    const float* wo_w = (const float*)d_in[9];
    const float* wo_b = (const float*)d_in[10];

    float* out = (float*)d_out;                    // [B,S,D]
    float* ctx = out + (size_t)NM * ND;            // [B,H,S,HD]

    dim3 gg(ND / 64, NM / 64);                     // (16, 128)

    gemm_nt_bias<<<gg, 256>>>(q, wq_w, wq_b, nullptr, 0, 0);   // -> g_Qp
    gemm_nt_bias<<<gg, 256>>>(k, wk_w, wk_b, nullptr, 0, 1);   // -> g_Kp
    gemm_nt_bias<<<gg, 256>>>(v, wv_w, wv_b, nullptr, 0, 2);   // -> g_Vp

    attn_kernel<<<dim3(NB * NH, NS / 128), 128>>>(ctx);        // -> ctx + g_mg

    gemm_nt_bias<<<gg, 256>>>(nullptr, wo_w, wo_b, out, 1, 3); // merged @ Wo^T + b
}

// round 4
// speedup vs baseline: 1.3626x; 1.3626x over previous
#include <cuda_runtime.h>
#include <cuda_bf16.h>
#include <cstdint>
#include <math.h>

// Problem shape (fixed)
#define NB  4
#define NS  2048
#define ND  1024
#define NH  16
#define NHD 64
#define NM  (NB * NS)   // 8192 rows

// Scratch (device globals: allocation-free)
__device__ float g_Qp[(size_t)NB * NS * ND];
__device__ float g_Kp[(size_t)NB * NS * ND];
__device__ float g_Vp[(size_t)NB * NS * ND];
__device__ float g_mg[(size_t)NB * NS * ND];

// ============================ PTX helpers ====================================
__device__ __forceinline__ uint32_t smem_u32(const void* p) {
    uint32_t a;
    asm("{ .reg .u64 t; cvta.to.shared.u64 t, %1; cvt.u32.u64 %0, t; }"
        : "=r"(a) : "l"(p));
    return a;
}

#define LDSM4(R0, R1, R2, R3, ADDR) \
    asm volatile("ldmatrix.sync.aligned.m8n8.x4.shared.b16 {%0,%1,%2,%3}, [%4];" \
                 : "=r"(R0), "=r"(R1), "=r"(R2), "=r"(R3) : "r"(ADDR))

#define MMA_BF16(C, A, B0, B1) \
    asm volatile("mma.sync.aligned.m16n8k16.row.col.f32.bf16.bf16.f32 " \
                 "{%0,%1,%2,%3}, {%4,%5,%6,%7}, {%8,%9}, {%0,%1,%2,%3};" \
                 : "+f"((C)[0]), "+f"((C)[1]), "+f"((C)[2]), "+f"((C)[3]) \
                 : "r"((A)[0]), "r"((A)[1]), "r"((A)[2]), "r"((A)[3]), \
                   "r"(B0), "r"(B1))

// Split fp32 -> (hi, lo) bf16 pairs, packed into uint2 (4 values = 8 bytes each)
__device__ __forceinline__ void bsplit4(float4 v, uint2& hi, uint2& lo) {
    __nv_bfloat16 h0 = __float2bfloat16(v.x);
    __nv_bfloat16 h1 = __float2bfloat16(v.y);
    __nv_bfloat16 h2 = __float2bfloat16(v.z);
    __nv_bfloat16 h3 = __float2bfloat16(v.w);
    __nv_bfloat16 l0 = __float2bfloat16(v.x - __bfloat162float(h0));
    __nv_bfloat16 l1 = __float2bfloat16(v.y - __bfloat162float(h1));
    __nv_bfloat16 l2 = __float2bfloat16(v.z - __bfloat162float(h2));
    __nv_bfloat16 l3 = __float2bfloat16(v.w - __bfloat162float(h3));
    hi.x = ((uint32_t)__bfloat16_as_ushort(h1) << 16) | __bfloat16_as_ushort(h0);
    hi.y = ((uint32_t)__bfloat16_as_ushort(h3) << 16) | __bfloat16_as_ushort(h2);
    lo.x = ((uint32_t)__bfloat16_as_ushort(l1) << 16) | __bfloat16_as_ushort(l0);
    lo.y = ((uint32_t)__bfloat16_as_ushort(l3) << 16) | __bfloat16_as_ushort(l2);
}

// Stage layout constants (bytes).  Row stride 80B = 32 bf16 data + pad.
// 8-row ldmatrix groups hit distinct 4-bank sets (r*20 mod 32) -> conflict-free.
#define ROWB   80
#define TILEB  (128 * ROWB)      // 10240
#define OFF_AHI 0
#define OFF_ALO (TILEB)
#define OFF_WHI (2 * TILEB)
#define OFF_WLO (3 * TILEB)
#define STAGEB  (4 * TILEB)      // 40960
#define SMEM_TOTAL (2 * STAGEB)  // 81920

// ============================================================================
// Warp-MMA split-bf16 GEMM:  C[M,N] = A[M,K] @ W[N,K]^T + bias[N]
// M=8192, N=K=1024.  CTA 128x128, 8 warps (2x4), warp tile 64x32.
// K-chunks of 32, double-buffered smem.  3 MMA products per chunk (hh,hl,lh).
// srcsel: 0 -> Aext, 1 -> g_mg.   dstsel: 0->g_Qp 1->g_Kp 2->g_Vp 3->Cext
// ============================================================================
__global__ __launch_bounds__(256, 2) void gemm_tc(
    const float* __restrict__ Aext, const float* __restrict__ W,
    const float* __restrict__ bias, float* __restrict__ Cext,
    int srcsel, int dstsel)
{
    const float* A = (srcsel == 0) ? Aext : g_mg;
    float* C = (dstsel == 0) ? g_Qp
             : (dstsel == 1) ? g_Kp
             : (dstsel == 2) ? g_Vp
             : Cext;

    extern __shared__ char dsm[];
    const uint32_t sbase = smem_u32(dsm);
    __shared__ float s_bias[128];

    const int t    = threadIdx.x;
    const int wid  = t >> 5;
    const int lane = t & 31;
    const int m0 = blockIdx.y * 128;
    const int n0 = blockIdx.x * 128;
    const int wm0 = (wid >> 2) * 64;   // warp m-offset inside CTA tile
    const int wn0 = (wid & 3) * 32;    // warp n-offset inside CTA tile

    if (t < 32) ((float4*)s_bias)[t] = *(const float4*)&bias[n0 + t * 4];

    // Per-lane ldmatrix base offsets (bytes) within a tile region.
    // A frag (m16xk16): rows wm0+mi*16+(lane&15), col-half (lane>>4)*8
    const uint32_t offA = (uint32_t)(wm0 + (lane & 15)) * ROWB
                        + (uint32_t)((lane >> 4) * 8) * 2;
    // B frag x4 (n16xk16): rows wn0+nj*16+((lane>>4)&1)*8+(lane&7),
    //                      col-half ((lane>>3)&1)*8
    const uint32_t offB = (uint32_t)(wn0 + ((lane >> 4) & 1) * 8 + (lane & 7)) * ROWB
                        + (uint32_t)(((lane >> 3) & 1) * 8) * 2;

    float acc[4][4][4];
    #pragma unroll
    for (int i = 0; i < 4; i++)
        #pragma unroll
        for (int j = 0; j < 4; j++)
            #pragma unroll
            for (int r = 0; r < 4; r++) acc[i][j][r] = 0.0f;

    // ---- stage chunk 0 ----
    {
        const int k0 = 0;
        char* dst = dsm;
        #pragma unroll
        for (int i = 0; i < 4; i++) {
            int f = i * 256 + t;           // 0..1023
            int row = f >> 3;
            int kg  = f & 7;
            uint32_t so = (uint32_t)row * ROWB + (uint32_t)kg * 8;
            float4 a = *(const float4*)&A[(size_t)(m0 + row) * ND + k0 + kg * 4];
            float4 w = *(const float4*)&W[(size_t)(n0 + row) * ND + k0 + kg * 4];
            uint2 hi, lo;
            bsplit4(a, hi, lo);
            *(uint2*)(dst + OFF_AHI + so) = hi;
            *(uint2*)(dst + OFF_ALO + so) = lo;
            bsplit4(w, hi, lo);
            *(uint2*)(dst + OFF_WHI + so) = hi;
            *(uint2*)(dst + OFF_WLO + so) = lo;
        }
    }
    __syncthreads();

    for (int c = 0; c < 32; c++) {
        const uint32_t sb = sbase + (uint32_t)(c & 1) * STAGEB;

        // ---- compute chunk c (2 k-steps of 16) ----
        #pragma unroll
        for (int ks = 0; ks < 2; ks++) {
            const uint32_t ka = (uint32_t)ks * 32;   // 16 cols * 2B
            uint32_t ah[16];
            uint32_t bb[8];

            // A-hi frags
            #pragma unroll
            for (int mi = 0; mi < 4; mi++)
                LDSM4(ah[mi*4+0], ah[mi*4+1], ah[mi*4+2], ah[mi*4+3],
                      sb + OFF_AHI + offA + ka + (uint32_t)mi * (16 * ROWB));
            // W-hi frags
            #pragma unroll
            for (int nj = 0; nj < 2; nj++)
                LDSM4(bb[nj*4+0], bb[nj*4+1], bb[nj*4+2], bb[nj*4+3],
                      sb + OFF_WHI + offB + ka + (uint32_t)nj * (16 * ROWB));
            // hi * hi
            #pragma unroll
            for (int mi = 0; mi < 4; mi++)
                #pragma unroll
                for (int ni = 0; ni < 4; ni++)
                    MMA_BF16(acc[mi][ni], &ah[mi*4],
                             bb[(ni >> 1) * 4 + (ni & 1) * 2],
                             bb[(ni >> 1) * 4 + (ni & 1) * 2 + 1]);
            // W-lo frags
            #pragma unroll
            for (int nj = 0; nj < 2; nj++)
                LDSM4(bb[nj*4+0], bb[nj*4+1], bb[nj*4+2], bb[nj*4+3],
                      sb + OFF_WLO + offB + ka + (uint32_t)nj * (16 * ROWB));
            // hi * lo
            #pragma unroll
            for (int mi = 0; mi < 4; mi++)
                #pragma unroll
                for (int ni = 0; ni < 4; ni++)
                    MMA_BF16(acc[mi][ni], &ah[mi*4],
                             bb[(ni >> 1) * 4 + (ni & 1) * 2],
                             bb[(ni >> 1) * 4 + (ni & 1) * 2 + 1]);
            // A-lo frags (overwrite ah) and W-hi frags again (overwrite bb)
            #pragma unroll
            for (int mi = 0; mi < 4; mi++)
                LDSM4(ah[mi*4+0], ah[mi*4+1], ah[mi*4+2], ah[mi*4+3],
                      sb + OFF_ALO + offA + ka + (uint32_t)mi * (16 * ROWB));
            #pragma unroll
            for (int nj = 0; nj < 2; nj++)
                LDSM4(bb[nj*4+0], bb[nj*4+1], bb[nj*4+2], bb[nj*4+3],
                      sb + OFF_WHI + offB + ka + (uint32_t)nj * (16 * ROWB));
            // lo * hi
            #pragma unroll
            for (int mi = 0; mi < 4; mi++)
                #pragma unroll
                for (int ni = 0; ni < 4; ni++)
                    MMA_BF16(acc[mi][ni], &ah[mi*4],
                             bb[(ni >> 1) * 4 + (ni & 1) * 2],
                             bb[(ni >> 1) * 4 + (ni & 1) * 2 + 1]);
        }

        // ---- stage chunk c+1 into the other buffer ----
        if (c + 1 < 32) {
            const int k0 = (c + 1) * 32;
            char* dst = dsm + ((c + 1) & 1) * STAGEB;
            #pragma unroll
            for (int i = 0; i < 4; i++) {
                int f = i * 256 + t;
                int row = f >> 3;
                int kg  = f & 7;
                uint32_t so = (uint32_t)row * ROWB + (uint32_t)kg * 8;
                float4 a = *(const float4*)&A[(size_t)(m0 + row) * ND + k0 + kg * 4];
                float4 w = *(const float4*)&W[(size_t)(n0 + row) * ND + k0 + kg * 4];
                uint2 hi, lo;
                bsplit4(a, hi, lo);
                *(uint2*)(dst + OFF_AHI + so) = hi;
                *(uint2*)(dst + OFF_ALO + so) = lo;
                bsplit4(w, hi, lo);
                *(uint2*)(dst + OFF_WHI + so) = hi;
                *(uint2*)(dst + OFF_WLO + so) = lo;
            }
        }
        __syncthreads();
    }

    // ---- epilogue: bias add + store ----
    const int cr = lane >> 2;          // 0..7
    const int cc = (lane & 3) * 2;     // 0,2,4,6
    #pragma unroll
    for (int mi = 0; mi < 4; mi++) {
        const int r0 = m0 + wm0 + mi * 16 + cr;
        #pragma unroll
        for (int ni = 0; ni < 4; ni++) {
            const int col = wn0 + ni * 8 + cc;
            const float b0 = s_bias[col];
            const float b1 = s_bias[col + 1];
            float2 o0, o1;
            o0.x = acc[mi][ni][0] + b0;
            o0.y = acc[mi][ni][1] + b1;
            o1.x = acc[mi][ni][2] + b0;
            o1.y = acc[mi][ni][3] + b1;
            *(float2*)&C[(size_t)r0 * ND + n0 + col] = o0;
            *(float2*)&C[(size_t)(r0 + 8) * ND + n0 + col] = o1;
        }
    }
}

// ----------------------------------------------------------------------------
// Flash-style attention (unchanged). Grid: (B*H, S/128), 128 threads.
// ----------------------------------------------------------------------------
__global__ __launch_bounds__(128) void attn_kernel(float* __restrict__ ctx_out)
{
    __shared__ float Ksm[64 * NHD];
    __shared__ float Vsm[64 * NHD];

    const int bh = blockIdx.x;
    const int b  = bh >> 4;
    const int h  = bh & 15;
    const int t  = threadIdx.x;
    const int qr = blockIdx.y * 128 + t;

    float q[NHD], acc[NHD];
    {
        const float4* qp = (const float4*)&g_Qp[((size_t)b * NS + qr) * ND + h * NHD];
        #pragma unroll
        for (int i = 0; i < 16; i++) {
            float4 v4 = qp[i];
            q[4 * i + 0] = v4.x; q[4 * i + 1] = v4.y;
            q[4 * i + 2] = v4.z; q[4 * i + 3] = v4.w;
        }
    }
    #pragma unroll
    for (int d = 0; d < NHD; d++) acc[d] = 0.0f;

    float m = -1e30f;
    float l = 0.0f;

    for (int kt = 0; kt < NS / 64; kt++) {
        #pragma unroll
        for (int i = 0; i < 8; i++) {
            int f   = i * 128 + t;
            int row = f >> 4;
            int c4  = f & 15;
            size_t g = ((size_t)b * NS + (size_t)kt * 64 + row) * ND + h * NHD + c4 * 4;
            ((float4*)Ksm)[f] = *(const float4*)&g_Kp[g];
            ((float4*)Vsm)[f] = *(const float4*)&g_Vp[g];
        }
        __syncthreads();

        #pragma unroll 4
        for (int j = 0; j < 64; j++) {
            const float4* kr = (const float4*)&Ksm[j * NHD];
            float s0 = 0.f, s1 = 0.f, s2 = 0.f, s3 = 0.f;
            #pragma unroll
            for (int d4 = 0; d4 < 16; d4++) {
                float4 kv = kr[d4];
                s0 += q[4 * d4 + 0] * kv.x;
                s1 += q[4 * d4 + 1] * kv.y;
                s2 += q[4 * d4 + 2] * kv.z;
                s3 += q[4 * d4 + 3] * kv.w;
            }
            float sj = ((s0 + s1) + (s2 + s3)) * 0.125f;

            if (sj > m) {
                float corr = __expf(m - sj);
                l *= corr;
                #pragma unroll
                for (int d = 0; d < NHD; d++) acc[d] *= corr;
                m = sj;
            }
            float w = __expf(sj - m);
            l += w;

            const float4* vr = (const float4*)&Vsm[j * NHD];
            #pragma unroll
            for (int d4 = 0; d4 < 16; d4++) {
                float4 vv = vr[d4];
                acc[4 * d4 + 0] += w * vv.x;
                acc[4 * d4 + 1] += w * vv.y;
                acc[4 * d4 + 2] += w * vv.z;
                acc[4 * d4 + 3] += w * vv.w;
            }
        }
        __syncthreads();
    }

    const float inv = 1.0f / l;
    float* cp = &ctx_out[(((size_t)b * NH + h) * NS + qr) * NHD];
    float* mp = &g_mg[((size_t)b * NS + qr) * ND + h * NHD];
    #pragma unroll
    for (int d4 = 0; d4 < 16; d4++) {
        float4 o;
        o.x = acc[4 * d4 + 0] * inv;
        o.y = acc[4 * d4 + 1] * inv;
        o.z = acc[4 * d4 + 2] * inv;
        o.w = acc[4 * d4 + 3] * inv;
        *(float4*)&cp[d4 * 4] = o;
        *(float4*)&mp[d4 * 4] = o;
    }
}

// ----------------------------------------------------------------------------
extern "C" void kernel_launch(void* const* d_in, const int* in_sizes, int n_in,
                              void* d_out, int out_size)
{
    (void)in_sizes; (void)n_in; (void)out_size;
    const float* q    = (const float*)d_in[0];
    const float* k    = (const float*)d_in[1];
    const float* v    = (const float*)d_in[2];
    const float* wq_w = (const float*)d_in[3];
    const float* wq_b = (const float*)d_in[4];
    const float* wk_w = (const float*)d_in[5];
    const float* wk_b = (const float*)d_in[6];
    const float* wv_w = (const float*)d_in[7];
    const float* wv_b = (const float*)d_in[8];
    const float* wo_w = (const float*)d_in[9];
    const float* wo_b = (const float*)d_in[10];

    float* out = (float*)d_out;                    // [B,S,D]
    float* ctx = out + (size_t)NM * ND;            // [B,H,S,HD]

    cudaFuncSetAttribute(gemm_tc, cudaFuncAttributeMaxDynamicSharedMemorySize,
                         SMEM_TOTAL);

    dim3 gg(ND / 128, NM / 128);                   // (8, 64)

    gemm_tc<<<gg, 256, SMEM_TOTAL>>>(q, wq_w, wq_b, nullptr, 0, 0);   // -> g_Qp
    gemm_tc<<<gg, 256, SMEM_TOTAL>>>(k, wk_w, wk_b, nullptr, 0, 1);   // -> g_Kp
    gemm_tc<<<gg, 256, SMEM_TOTAL>>>(v, wv_w, wv_b, nullptr, 0, 2);   // -> g_Vp

    attn_kernel<<<dim3(NB * NH, NS / 128), 128>>>(ctx);               // -> ctx + g_mg

    gemm_tc<<<gg, 256, SMEM_TOTAL>>>(nullptr, wo_w, wo_b, out, 1, 3); // -> out
}

// round 7
// speedup vs baseline: 3.4341x; 2.5203x over previous
#include <cuda_runtime.h>
#include <cuda_bf16.h>
#include <cstdint>
#include <math.h>

// Problem shape (fixed)
#define NB  4
#define NS  2048
#define ND  1024
#define NH  16
#define NHD 64
#define NM  (NB * NS)   // 8192 rows

// Scratch (device globals: allocation-free)
// Q/K/V stored as split-bf16 planes (hi + lo); Q pre-scaled by 0.125*log2(e).
__device__ __nv_bfloat16 g_Qh[(size_t)NM * ND];
__device__ __nv_bfloat16 g_Ql[(size_t)NM * ND];
__device__ __nv_bfloat16 g_Kh[(size_t)NM * ND];
__device__ __nv_bfloat16 g_Kl[(size_t)NM * ND];
__device__ __nv_bfloat16 g_Vh[(size_t)NM * ND];
__device__ __nv_bfloat16 g_Vl[(size_t)NM * ND];
__device__ float g_mg[(size_t)NM * ND];

// ============================ PTX helpers ====================================
__device__ __forceinline__ uint32_t smem_u32(const void* p) {
    uint32_t a;
    asm("{ .reg .u64 t; cvta.to.shared.u64 t, %1; cvt.u32.u64 %0, t; }"
        : "=r"(a) : "l"(p));
    return a;
}
__device__ __forceinline__ float ex2f(float x) {
    float y;
    asm("ex2.approx.ftz.f32 %0, %1;" : "=f"(y) : "f"(x));
    return y;
}

#define LDSM4(R0, R1, R2, R3, ADDR) \
    asm volatile("ldmatrix.sync.aligned.m8n8.x4.shared.b16 {%0,%1,%2,%3}, [%4];" \
                 : "=r"(R0), "=r"(R1), "=r"(R2), "=r"(R3) : "r"(ADDR))
#define LDSM4T(R0, R1, R2, R3, ADDR) \
    asm volatile("ldmatrix.sync.aligned.m8n8.x4.trans.shared.b16 {%0,%1,%2,%3}, [%4];" \
                 : "=r"(R0), "=r"(R1), "=r"(R2), "=r"(R3) : "r"(ADDR))

#define MMA_BF16(C, A, B0, B1) \
    asm volatile("mma.sync.aligned.m16n8k16.row.col.f32.bf16.bf16.f32 " \
                 "{%0,%1,%2,%3}, {%4,%5,%6,%7}, {%8,%9}, {%0,%1,%2,%3};" \
                 : "+f"((C)[0]), "+f"((C)[1]), "+f"((C)[2]), "+f"((C)[3]) \
                 : "r"((A)[0]), "r"((A)[1]), "r"((A)[2]), "r"((A)[3]), \
                   "r"(B0), "r"(B1))

// Split fp32 -> (hi, lo) bf16 pairs, packed into uint2 (4 values = 8 bytes each)
__device__ __forceinline__ void bsplit4(float4 v, uint2& hi, uint2& lo) {
    __nv_bfloat16 h0 = __float2bfloat16(v.x);
    __nv_bfloat16 h1 = __float2bfloat16(v.y);
    __nv_bfloat16 h2 = __float2bfloat16(v.z);
    __nv_bfloat16 h3 = __float2bfloat16(v.w);
    __nv_bfloat16 l0 = __float2bfloat16(v.x - __bfloat162float(h0));
    __nv_bfloat16 l1 = __float2bfloat16(v.y - __bfloat162float(h1));
    __nv_bfloat16 l2 = __float2bfloat16(v.z - __bfloat162float(h2));
    __nv_bfloat16 l3 = __float2bfloat16(v.w - __bfloat162float(h3));
    hi.x = ((uint32_t)__bfloat16_as_ushort(h1) << 16) | __bfloat16_as_ushort(h0);
    hi.y = ((uint32_t)__bfloat16_as_ushort(h3) << 16) | __bfloat16_as_ushort(h2);
    lo.x = ((uint32_t)__bfloat16_as_ushort(l1) << 16) | __bfloat16_as_ushort(l0);
    lo.y = ((uint32_t)__bfloat16_as_ushort(l3) << 16) | __bfloat16_as_ushort(l2);
}
// Split two fp32 values into packed bf16x2 hi + lo words.
__device__ __forceinline__ void psplit2(float a, float b, uint32_t& hi, uint32_t& lo) {
    __nv_bfloat16 ha = __float2bfloat16(a), hb = __float2bfloat16(b);
    __nv_bfloat16 la = __float2bfloat16(a - __bfloat162float(ha));
    __nv_bfloat16 lb = __float2bfloat16(b - __bfloat162float(hb));
    hi = ((uint32_t)__bfloat16_as_ushort(hb) << 16) | __bfloat16_as_ushort(ha);
    lo = ((uint32_t)__bfloat16_as_ushort(lb) << 16) | __bfloat16_as_ushort(la);
}

// Stage layout (GEMM): rows of 32 bf16 (64B) + 16B pad.
#define ROWB   80
#define TILEB  (128 * ROWB)
#define OFF_AHI 0
#define OFF_ALO (TILEB)
#define OFF_WHI (2 * TILEB)
#define OFF_WLO (3 * TILEB)
#define STAGEB  (4 * TILEB)
#define GSMEM_TOTAL (2 * STAGEB)  // 81920

// Q pre-scale: 1/sqrt(64) * log2(e)
#define QSCALE 0.18033688011112042f

// ============================================================================
// Warp-MMA split-bf16 GEMM:  C[M,N] = A[M,K] @ W[N,K]^T + bias[N]
// dstsel 0/1/2: write split-bf16 planes (Q scaled), 3: fp32 to Cext.
// srcsel: 0 -> Aext, 1 -> g_mg.
// ============================================================================
__global__ __launch_bounds__(256, 2) void gemm_tc(
    const float* __restrict__ Aext, const float* __restrict__ W,
    const float* __restrict__ bias, float* __restrict__ Cext,
    int srcsel, int dstsel)
{
    const float* A = (srcsel == 0) ? Aext : g_mg;

    extern __shared__ char dsm[];
    const uint32_t sbase = smem_u32(dsm);
    __shared__ float s_bias[128];

    const int t    = threadIdx.x;
    const int wid  = t >> 5;
    const int lane = t & 31;
    const int m0 = blockIdx.y * 128;
    const int n0 = blockIdx.x * 128;
    const int wm0 = (wid >> 2) * 64;
    const int wn0 = (wid & 3) * 32;

    if (t < 32) ((float4*)s_bias)[t] = *(const float4*)&bias[n0 + t * 4];

    const uint32_t offA = (uint32_t)(wm0 + (lane & 15)) * ROWB
                        + (uint32_t)((lane >> 4) * 8) * 2;
    const uint32_t offB = (uint32_t)(wn0 + ((lane >> 4) & 1) * 8 + (lane & 7)) * ROWB
                        + (uint32_t)(((lane >> 3) & 1) * 8) * 2;

    float acc[4][4][4];
    #pragma unroll
    for (int i = 0; i < 4; i++)
        #pragma unroll
        for (int j = 0; j < 4; j++)
            #pragma unroll
            for (int r = 0; r < 4; r++) acc[i][j][r] = 0.0f;

    // stage chunk 0
    {
        char* dst = dsm;
        #pragma unroll
        for (int i = 0; i < 4; i++) {
            int f = i * 256 + t;
            int row = f >> 3;
            int kg  = f & 7;
            uint32_t so = (uint32_t)row * ROWB + (uint32_t)kg * 8;
            float4 a = *(const float4*)&A[(size_t)(m0 + row) * ND + kg * 4];
            float4 w = *(const float4*)&W[(size_t)(n0 + row) * ND + kg * 4];
            uint2 hi, lo;
            bsplit4(a, hi, lo);
            *(uint2*)(dst + OFF_AHI + so) = hi;
            *(uint2*)(dst + OFF_ALO + so) = lo;
            bsplit4(w, hi, lo);
            *(uint2*)(dst + OFF_WHI + so) = hi;
            *(uint2*)(dst + OFF_WLO + so) = lo;
        }
    }
    __syncthreads();

    for (int c = 0; c < 32; c++) {
        const uint32_t sb = sbase + (uint32_t)(c & 1) * STAGEB;

        #pragma unroll
        for (int ks = 0; ks < 2; ks++) {
            const uint32_t ka = (uint32_t)ks * 32;
            uint32_t ah[16];
            uint32_t bb[8];

            #pragma unroll
            for (int mi = 0; mi < 4; mi++)
                LDSM4(ah[mi*4+0], ah[mi*4+1], ah[mi*4+2], ah[mi*4+3],
                      sb + OFF_AHI + offA + ka + (uint32_t)mi * (16 * ROWB));
            #pragma unroll
            for (int nj = 0; nj < 2; nj++)
                LDSM4(bb[nj*4+0], bb[nj*4+1], bb[nj*4+2], bb[nj*4+3],
                      sb + OFF_WHI + offB + ka + (uint32_t)nj * (16 * ROWB));
            #pragma unroll
            for (int mi = 0; mi < 4; mi++)
                #pragma unroll
                for (int ni = 0; ni < 4; ni++)
                    MMA_BF16(acc[mi][ni], &ah[mi*4],
                             bb[(ni >> 1) * 4 + (ni & 1) * 2],
                             bb[(ni >> 1) * 4 + (ni & 1) * 2 + 1]);
            #pragma unroll
            for (int nj = 0; nj < 2; nj++)
                LDSM4(bb[nj*4+0], bb[nj*4+1], bb[nj*4+2], bb[nj*4+3],
                      sb + OFF_WLO + offB + ka + (uint32_t)nj * (16 * ROWB));
            #pragma unroll
            for (int mi = 0; mi < 4; mi++)
                #pragma unroll
                for (int ni = 0; ni < 4; ni++)
                    MMA_BF16(acc[mi][ni], &ah[mi*4],
                             bb[(ni >> 1) * 4 + (ni & 1) * 2],
                             bb[(ni >> 1) * 4 + (ni & 1) * 2 + 1]);
            #pragma unroll
            for (int mi = 0; mi < 4; mi++)
                LDSM4(ah[mi*4+0], ah[mi*4+1], ah[mi*4+2], ah[mi*4+3],
                      sb + OFF_ALO + offA + ka + (uint32_t)mi * (16 * ROWB));
            #pragma unroll
            for (int nj = 0; nj < 2; nj++)
                LDSM4(bb[nj*4+0], bb[nj*4+1], bb[nj*4+2], bb[nj*4+3],
                      sb + OFF_WHI + offB + ka + (uint32_t)nj * (16 * ROWB));
            #pragma unroll
            for (int mi = 0; mi < 4; mi++)
                #pragma unroll
                for (int ni = 0; ni < 4; ni++)
                    MMA_BF16(acc[mi][ni], &ah[mi*4],
                             bb[(ni >> 1) * 4 + (ni & 1) * 2],
                             bb[(ni >> 1) * 4 + (ni & 1) * 2 + 1]);
        }

        if (c + 1 < 32) {
            const int k0 = (c + 1) * 32;
            char* dst = dsm + ((c + 1) & 1) * STAGEB;
            #pragma unroll
            for (int i = 0; i < 4; i++) {
                int f = i * 256 + t;
                int row = f >> 3;
                int kg  = f & 7;
                uint32_t so = (uint32_t)row * ROWB + (uint32_t)kg * 8;
                float4 a = *(const float4*)&A[(size_t)(m0 + row) * ND + k0 + kg * 4];
                float4 w = *(const float4*)&W[(size_t)(n0 + row) * ND + k0 + kg * 4];
                uint2 hi, lo;
                bsplit4(a, hi, lo);
                *(uint2*)(dst + OFF_AHI + so) = hi;
                *(uint2*)(dst + OFF_ALO + so) = lo;
                bsplit4(w, hi, lo);
                *(uint2*)(dst + OFF_WHI + so) = hi;
                *(uint2*)(dst + OFF_WLO + so) = lo;
            }
        }
        __syncthreads();
    }

    // ---- epilogue ----
    const int cr = lane >> 2;
    const int cc = (lane & 3) * 2;
    if (dstsel < 3) {
        const float qs = (dstsel == 0) ? QSCALE : 1.0f;
        __nv_bfloat16* Ph = (dstsel == 0) ? g_Qh : (dstsel == 1) ? g_Kh : g_Vh;
        __nv_bfloat16* Pl = (dstsel == 0) ? g_Ql : (dstsel == 1) ? g_Kl : g_Vl;
        #pragma unroll
        for (int mi = 0; mi < 4; mi++) {
            const int r0 = m0 + wm0 + mi * 16 + cr;
            #pragma unroll
            for (int ni = 0; ni < 4; ni++) {
                const int col = wn0 + ni * 8 + cc;
                const float b0 = s_bias[col];
                const float b1 = s_bias[col + 1];
                float v0 = (acc[mi][ni][0] + b0) * qs;
                float v1 = (acc[mi][ni][1] + b1) * qs;
                float v2 = (acc[mi][ni][2] + b0) * qs;
                float v3 = (acc[mi][ni][3] + b1) * qs;
                uint32_t hi, lo;
                psplit2(v0, v1, hi, lo);
                *(uint32_t*)&Ph[(size_t)r0 * ND + n0 + col] = hi;
                *(uint32_t*)&Pl[(size_t)r0 * ND + n0 + col] = lo;
                psplit2(v2, v3, hi, lo);
                *(uint32_t*)&Ph[(size_t)(r0 + 8) * ND + n0 + col] = hi;
                *(uint32_t*)&Pl[(size_t)(r0 + 8) * ND + n0 + col] = lo;
            }
        }
    } else {
        #pragma unroll
        for (int mi = 0; mi < 4; mi++) {
            const int r0 = m0 + wm0 + mi * 16 + cr;
            #pragma unroll
            for (int ni = 0; ni < 4; ni++) {
                const int col = wn0 + ni * 8 + cc;
                const float b0 = s_bias[col];
                const float b1 = s_bias[col + 1];
                float2 o0, o1;
                o0.x = acc[mi][ni][0] + b0;
                o0.y = acc[mi][ni][1] + b1;
                o1.x = acc[mi][ni][2] + b0;
                o1.y = acc[mi][ni][3] + b1;
                *(float2*)&Cext[(size_t)r0 * ND + n0 + col] = o0;
                *(float2*)&Cext[(size_t)(r0 + 8) * ND + n0 + col] = o1;
            }
        }
    }
}

// ============================================================================
// Tensor-core flash attention. Grid (B*NH, NS/128), 256 threads (8 warps x 16 rows).
// Reads split-bf16 Q (pre-scaled into log2 domain) / K / V; writes ctx + g_mg.
// ============================================================================
#define AROWB 144           // 64 bf16 (128B) + 16B pad
#define OKH 0
#define OKL 9216
#define OVH 18432
#define OVL 27648

__global__ __launch_bounds__(256) void attn_tc(float* __restrict__ ctx_out)
{
    __shared__ __align__(16) char sm[36864];
    const uint32_t sb = smem_u32(sm);
    const int t = threadIdx.x, wid = t >> 5, lane = t & 31;
    const int b = blockIdx.x >> 4, h = blockIdx.x & 15;
    const int q0 = blockIdx.y * 128;

    // ---- stage Q tile (128 x 64, hi/lo), then load frags ----
    #pragma unroll
    for (int i = 0; i < 4; i++) {
        int f = i * 256 + t, row = f >> 3, dg = f & 7;
        size_t g = ((size_t)b * NS + q0 + row) * ND + h * 64 + dg * 8;
        uint32_t so = (uint32_t)row * AROWB + (uint32_t)dg * 16;
        *(uint4*)(sm + so)         = *(const uint4*)&g_Qh[g];
        *(uint4*)(sm + 18432 + so) = *(const uint4*)&g_Ql[g];
    }
    __syncthreads();

    uint32_t qh[4][4], ql[4][4];
    const uint32_t offA = (uint32_t)(wid * 16 + (lane & 15)) * AROWB
                        + (uint32_t)((lane >> 4) * 8) * 2;
    #pragma unroll
    for (int ks = 0; ks < 4; ks++) {
        LDSM4(qh[ks][0], qh[ks][1], qh[ks][2], qh[ks][3], sb + offA + ks * 32);
        LDSM4(ql[ks][0], ql[ks][1], ql[ks][2], ql[ks][3], sb + 18432 + offA + ks * 32);
    }
    __syncthreads();

    float ctx[8][4];
    #pragma unroll
    for (int i = 0; i < 8; i++)
        #pragma unroll
        for (int j = 0; j < 4; j++) ctx[i][j] = 0.0f;
    float m0 = -1e30f, m1 = -1e30f, l0 = 0.0f, l1 = 0.0f;

    const uint32_t offBs = (uint32_t)(((lane >> 4) & 1) * 8 + (lane & 7)) * AROWB
                         + (uint32_t)(((lane >> 3) & 1) * 8) * 2;
    const uint32_t offBt = (uint32_t)(lane & 15) * AROWB + (uint32_t)((lane >> 4) * 8) * 2;

    for (int kt = 0; kt < NS / 64; kt++) {
        // ---- stage K/V tile (64 keys x 64 dims, hi/lo) ----
        #pragma unroll
        for (int i = 0; i < 2; i++) {
            int f = i * 256 + t, row = f >> 3, dg = f & 7;
            size_t g = ((size_t)b * NS + kt * 64 + row) * ND + h * 64 + dg * 8;
            uint32_t so = (uint32_t)row * AROWB + (uint32_t)dg * 16;
            *(uint4*)(sm + OKH + so) = *(const uint4*)&g_Kh[g];
            *(uint4*)(sm + OKL + so) = *(const uint4*)&g_Kl[g];
            *(uint4*)(sm + OVH + so) = *(const uint4*)&g_Vh[g];
            *(uint4*)(sm + OVL + so) = *(const uint4*)&g_Vl[g];
        }
        __syncthreads();

        // ---- scores: S = Q . K^T  (split-bf16, 3 products) ----
        float s[8][4];
        #pragma unroll
        for (int i = 0; i < 8; i++)
            #pragma unroll
            for (int j = 0; j < 4; j++) s[i][j] = 0.0f;

        #pragma unroll
        for (int ks = 0; ks < 4; ks++) {
            #pragma unroll
            for (int nbp = 0; nbp < 4; nbp++) {
                uint32_t kh[4], kl[4];
                uint32_t a = sb + (uint32_t)nbp * (16 * AROWB) + (uint32_t)ks * 32 + offBs;
                LDSM4(kh[0], kh[1], kh[2], kh[3], a + OKH);
                LDSM4(kl[0], kl[1], kl[2], kl[3], a + OKL);
                MMA_BF16(s[2*nbp],   qh[ks], kh[0], kh[1]);
                MMA_BF16(s[2*nbp+1], qh[ks], kh[2], kh[3]);
                MMA_BF16(s[2*nbp],   qh[ks], kl[0], kl[1]);
                MMA_BF16(s[2*nbp+1], qh[ks], kl[2], kl[3]);
                MMA_BF16(s[2*nbp],   ql[ks], kh[0], kh[1]);
                MMA_BF16(s[2*nbp+1], ql[ks], kh[2], kh[3]);
            }
        }

        // ---- online softmax (scores already in log2 domain) ----
        float mn0 = s[0][0], mn1 = s[0][2];
        #pragma unroll
        for (int nb = 0; nb < 8; nb++) {
            mn0 = fmaxf(mn0, fmaxf(s[nb][0], s[nb][1]));
            mn1 = fmaxf(mn1, fmaxf(s[nb][2], s[nb][3]));
        }
        mn0 = fmaxf(mn0, __shfl_xor_sync(0xffffffffu, mn0, 1));
        mn0 = fmaxf(mn0, __shfl_xor_sync(0xffffffffu, mn0, 2));
        mn1 = fmaxf(mn1, __shfl_xor_sync(0xffffffffu, mn1, 1));
        mn1 = fmaxf(mn1, __shfl_xor_sync(0xffffffffu, mn1, 2));
        float nm0 = fmaxf(m0, mn0), nm1 = fmaxf(m1, mn1);
        float c0 = ex2f(m0 - nm0), c1 = ex2f(m1 - nm1);
        m0 = nm0; m1 = nm1;

        float sum0 = 0.0f, sum1 = 0.0f;
        #pragma unroll
        for (int nb = 0; nb < 8; nb++) {
            s[nb][0] = ex2f(s[nb][0] - m0);
            s[nb][1] = ex2f(s[nb][1] - m0);
            s[nb][2] = ex2f(s[nb][2] - m1);
            s[nb][3] = ex2f(s[nb][3] - m1);
            sum0 += s[nb][0] + s[nb][1];
            sum1 += s[nb][2] + s[nb][3];
        }
        sum0 += __shfl_xor_sync(0xffffffffu, sum0, 1);
        sum0 += __shfl_xor_sync(0xffffffffu, sum0, 2);
        sum1 += __shfl_xor_sync(0xffffffffu, sum1, 1);
        sum1 += __shfl_xor_sync(0xffffffffu, sum1, 2);
        l0 = l0 * c0 + sum0;
        l1 = l1 * c1 + sum1;
        #pragma unroll
        for (int db = 0; db < 8; db++) {
            ctx[db][0] *= c0; ctx[db][1] *= c0;
            ctx[db][2] *= c1; ctx[db][3] *= c1;
        }

        // ---- P frags: C-frag -> A-frag identity, split hi/lo ----
        uint32_t pah[4][4], pal[4][4];
        #pragma unroll
        for (int ks = 0; ks < 4; ks++) {
            const int e = 2 * ks, o = 2 * ks + 1;
            psplit2(s[e][0], s[e][1], pah[ks][0], pal[ks][0]);
            psplit2(s[e][2], s[e][3], pah[ks][1], pal[ks][1]);
            psplit2(s[o][0], s[o][1], pah[ks][2], pal[ks][2]);
            psplit2(s[o][2], s[o][3], pah[ks][3], pal[ks][3]);
        }

        // ---- ctx += P . V  (split-bf16, 3 products; V via trans ldmatrix) ----
        #pragma unroll
        for (int ks = 0; ks < 4; ks++) {
            #pragma unroll
            for (int dbp = 0; dbp < 4; dbp++) {
                uint32_t vh[4], vl[4];
                uint32_t a = sb + (uint32_t)ks * (16 * AROWB) + (uint32_t)dbp * 32 + offBt;
                LDSM4T(vh[0], vh[1], vh[2], vh[3], a + OVH);
                LDSM4T(vl[0], vl[1], vl[2], vl[3], a + OVL);
                MMA_BF16(ctx[2*dbp],   pah[ks], vh[0], vh[1]);
                MMA_BF16(ctx[2*dbp+1], pah[ks], vh[2], vh[3]);
                MMA_BF16(ctx[2*dbp],   pah[ks], vl[0], vl[1]);
                MMA_BF16(ctx[2*dbp+1], pah[ks], vl[2], vl[3]);
                MMA_BF16(ctx[2*dbp],   pal[ks], vh[0], vh[1]);
                MMA_BF16(ctx[2*dbp+1], pal[ks], vh[2], vh[3]);
            }
        }
        __syncthreads();
    }

    // ---- write ctx (normalized) to ctx_out and merged g_mg ----
    const float i0 = 1.0f / l0, i1 = 1.0f / l1;
    const int r0 = q0 + wid * 16 + (lane >> 2);
    #pragma unroll
    for (int db = 0; db < 8; db++) {
        const int col = db * 8 + (lane & 3) * 2;
        float2 o0, o1;
        o0.x = ctx[db][0] * i0; o0.y = ctx[db][1] * i0;
        o1.x = ctx[db][2] * i1; o1.y = ctx[db][3] * i1;
        *(float2*)&ctx_out[(((size_t)b * NH + h) * NS + r0) * NHD + col]     = o0;
        *(float2*)&ctx_out[(((size_t)b * NH + h) * NS + r0 + 8) * NHD + col] = o1;
        *(float2*)&g_mg[((size_t)b * NS + r0) * ND + h * NHD + col]          = o0;
        *(float2*)&g_mg[((size_t)b * NS + r0 + 8) * ND + h * NHD + col]      = o1;
    }
}

// ----------------------------------------------------------------------------
extern "C" void kernel_launch(void* const* d_in, const int* in_sizes, int n_in,
                              void* d_out, int out_size)
{
    (void)in_sizes; (void)n_in; (void)out_size;
    const float* q    = (const float*)d_in[0];
    const float* k    = (const float*)d_in[1];
    const float* v    = (const float*)d_in[2];
    const float* wq_w = (const float*)d_in[3];
    const float* wq_b = (const float*)d_in[4];
    const float* wk_w = (const float*)d_in[5];
    const float* wk_b = (const float*)d_in[6];
    const float* wv_w = (const float*)d_in[7];
    const float* wv_b = (const float*)d_in[8];
    const float* wo_w = (const float*)d_in[9];
    const float* wo_b = (const float*)d_in[10];

    float* out = (float*)d_out;                    // [B,S,D]
    float* ctx = out + (size_t)NM * ND;            // [B,H,S,HD]

    cudaFuncSetAttribute(gemm_tc, cudaFuncAttributeMaxDynamicSharedMemorySize,
                         GSMEM_TOTAL);

    dim3 gg(ND / 128, NM / 128);                   // (8, 64)

    gemm_tc<<<gg, 256, GSMEM_TOTAL>>>(q, wq_w, wq_b, nullptr, 0, 0);   // -> Q split (scaled)
    gemm_tc<<<gg, 256, GSMEM_TOTAL>>>(k, wk_w, wk_b, nullptr, 0, 1);   // -> K split
    gemm_tc<<<gg, 256, GSMEM_TOTAL>>>(v, wv_w, wv_b, nullptr, 0, 2);   // -> V split

    attn_tc<<<dim3(NB * NH, NS / 128), 256>>>(ctx);                    // -> ctx + g_mg

    gemm_tc<<<gg, 256, GSMEM_TOTAL>>>(nullptr, wo_w, wo_b, out, 1, 3); // -> out
}

// round 8
// speedup vs baseline: 3.9417x; 1.1478x over previous
#include <cuda_runtime.h>
#include <cuda_bf16.h>
#include <cstdint>
#include <math.h>

// Problem shape (fixed)
#define NB  4
#define NS  2048
#define ND  1024
#define NH  16
#define NHD 64
#define NM  (NB * NS)   // 8192 rows
#define A8M ((size_t)NM * ND)    // 8388608
#define W1M ((size_t)ND * ND)    // 1048576

// ---- Scratch (device globals: allocation-free) ----
// Pre-split bf16 planes of the raw inputs (q,k,v) and the 4 weight matrices.
__device__ __nv_bfloat16 g_Ah[3 * A8M];
__device__ __nv_bfloat16 g_Al[3 * A8M];
__device__ __nv_bfloat16 g_Wph[4 * W1M];
__device__ __nv_bfloat16 g_Wpl[4 * W1M];
// Projected Q/K/V planes (Q pre-scaled by 0.125*log2(e)).
__device__ __nv_bfloat16 g_Qh[A8M];
__device__ __nv_bfloat16 g_Ql[A8M];
__device__ __nv_bfloat16 g_Kh[A8M];
__device__ __nv_bfloat16 g_Kl[A8M];
__device__ __nv_bfloat16 g_Vh[A8M];
__device__ __nv_bfloat16 g_Vl[A8M];
// Merged attention output planes (input to the O projection).
__device__ __nv_bfloat16 g_Mh[A8M];
__device__ __nv_bfloat16 g_Ml[A8M];

// ============================ PTX helpers ====================================
__device__ __forceinline__ uint32_t smem_u32(const void* p) {
    uint32_t a;
    asm("{ .reg .u64 t; cvta.to.shared.u64 t, %1; cvt.u32.u64 %0, t; }"
        : "=r"(a) : "l"(p));
    return a;
}
__device__ __forceinline__ float ex2f(float x) {
    float y;
    asm("ex2.approx.ftz.f32 %0, %1;" : "=f"(y) : "f"(x));
    return y;
}

#define LDSM4(R0, R1, R2, R3, ADDR) \
    asm volatile("ldmatrix.sync.aligned.m8n8.x4.shared.b16 {%0,%1,%2,%3}, [%4];" \
                 : "=r"(R0), "=r"(R1), "=r"(R2), "=r"(R3) : "r"(ADDR))
#define LDSM4T(R0, R1, R2, R3, ADDR) \
    asm volatile("ldmatrix.sync.aligned.m8n8.x4.trans.shared.b16 {%0,%1,%2,%3}, [%4];" \
                 : "=r"(R0), "=r"(R1), "=r"(R2), "=r"(R3) : "r"(ADDR))

#define MMA_BF16(C, A, B0, B1) \
    asm volatile("mma.sync.aligned.m16n8k16.row.col.f32.bf16.bf16.f32 " \
                 "{%0,%1,%2,%3}, {%4,%5,%6,%7}, {%8,%9}, {%0,%1,%2,%3};" \
                 : "+f"((C)[0]), "+f"((C)[1]), "+f"((C)[2]), "+f"((C)[3]) \
                 : "r"((A)[0]), "r"((A)[1]), "r"((A)[2]), "r"((A)[3]), \
                   "r"(B0), "r"(B1))

#define CP_A16(DST, SRC) \
    asm volatile("cp.async.cg.shared.global [%0], [%1], 16;" \
                 :: "r"(DST), "l"(SRC) : "memory")
#define CP_COMMIT() asm volatile("cp.async.commit_group;" ::: "memory")
#define CP_WAIT0()  asm volatile("cp.async.wait_group 0;" ::: "memory")
#define CP_WAIT1()  asm volatile("cp.async.wait_group 1;" ::: "memory")

// Split fp32 -> (hi, lo) bf16 pairs, packed into uint2 (4 values = 8 bytes each)
__device__ __forceinline__ void bsplit4(float4 v, uint2& hi, uint2& lo) {
    __nv_bfloat16 h0 = __float2bfloat16(v.x);
    __nv_bfloat16 h1 = __float2bfloat16(v.y);
    __nv_bfloat16 h2 = __float2bfloat16(v.z);
    __nv_bfloat16 h3 = __float2bfloat16(v.w);
    __nv_bfloat16 l0 = __float2bfloat16(v.x - __bfloat162float(h0));
    __nv_bfloat16 l1 = __float2bfloat16(v.y - __bfloat162float(h1));
    __nv_bfloat16 l2 = __float2bfloat16(v.z - __bfloat162float(h2));
    __nv_bfloat16 l3 = __float2bfloat16(v.w - __bfloat162float(h3));
    hi.x = ((uint32_t)__bfloat16_as_ushort(h1) << 16) | __bfloat16_as_ushort(h0);
    hi.y = ((uint32_t)__bfloat16_as_ushort(h3) << 16) | __bfloat16_as_ushort(h2);
    lo.x = ((uint32_t)__bfloat16_as_ushort(l1) << 16) | __bfloat16_as_ushort(l0);
    lo.y = ((uint32_t)__bfloat16_as_ushort(l3) << 16) | __bfloat16_as_ushort(l2);
}
__device__ __forceinline__ void psplit2(float a, float b, uint32_t& hi, uint32_t& lo) {
    __nv_bfloat16 ha = __float2bfloat16(a), hb = __float2bfloat16(b);
    __nv_bfloat16 la = __float2bfloat16(a - __bfloat162float(ha));
    __nv_bfloat16 lb = __float2bfloat16(b - __bfloat162float(hb));
    hi = ((uint32_t)__bfloat16_as_ushort(hb) << 16) | __bfloat16_as_ushort(ha);
    lo = ((uint32_t)__bfloat16_as_ushort(lb) << 16) | __bfloat16_as_ushort(la);
}

// Q pre-scale: 1/sqrt(64) * log2(e)
#define QSCALE 0.18033688011112042f

// ============================================================================
// split_plane: fp32 -> (hi, lo) bf16 planes.
// sel 0..2: inputs q/k/v (8M elems) -> g_Ah/g_Al + sel*A8M
// sel 3..6: weights wq/wk/wv/wo (1M elems) -> g_Wph/g_Wpl + (sel-3)*W1M
// ============================================================================
__global__ void split_plane(const float* __restrict__ src, int sel)
{
    __nv_bfloat16 *H, *L;
    size_t n;
    if (sel < 3) { H = g_Ah + (size_t)sel * A8M; L = g_Al + (size_t)sel * A8M; n = A8M; }
    else         { H = g_Wph + (size_t)(sel - 3) * W1M; L = g_Wpl + (size_t)(sel - 3) * W1M; n = W1M; }
    const size_t n4 = n >> 2;
    const size_t stride = (size_t)gridDim.x * blockDim.x;
    for (size_t i = (size_t)blockIdx.x * blockDim.x + threadIdx.x; i < n4; i += stride) {
        float4 v = ((const float4*)src)[i];
        uint2 hi, lo;
        bsplit4(v, hi, lo);
        ((uint2*)H)[i] = hi;
        ((uint2*)L)[i] = lo;
    }
}

// Stage layout (GEMM): rows of 32 bf16 (64B) + 16B pad.
#define ROWB   80
#define TILEB  (128 * ROWB)
#define OFF_AHI 0
#define OFF_ALO (TILEB)
#define OFF_WHI (2 * TILEB)
#define OFF_WLO (3 * TILEB)
#define STAGEB  (4 * TILEB)
#define GSMEM_TOTAL (2 * STAGEB)  // 81920

// ============================================================================
// Warp-MMA split-bf16 GEMM over pre-split planes, cp.async double-buffered.
// C[M,N] = A[M,K] @ W[N,K]^T + bias[N].  M=8192, N=K=1024.
// asel 0..2: g_Ah/g_Al + asel*A8M; asel 3: merged planes g_Mh/g_Ml.
// wsel 0..3 selects weight planes.  dstsel 0/1/2: Q/K/V split planes
// (Q scaled); 3: fp32 Cext.
// ============================================================================
__global__ __launch_bounds__(256, 2) void gemm_tc(
    const float* __restrict__ bias, float* __restrict__ Cext,
    int asel, int wsel, int dstsel)
{
    const __nv_bfloat16 *Ah, *Al;
    if (asel < 3) { Ah = g_Ah + (size_t)asel * A8M; Al = g_Al + (size_t)asel * A8M; }
    else          { Ah = g_Mh; Al = g_Ml; }
    const __nv_bfloat16* Wh = g_Wph + (size_t)wsel * W1M;
    const __nv_bfloat16* Wl = g_Wpl + (size_t)wsel * W1M;

    extern __shared__ char dsm[];
    const uint32_t sbase = smem_u32(dsm);
    __shared__ float s_bias[128];

    const int t    = threadIdx.x;
    const int wid  = t >> 5;
    const int lane = t & 31;
    const int m0 = blockIdx.y * 128;
    const int n0 = blockIdx.x * 128;
    const int wm0 = (wid >> 2) * 64;
    const int wn0 = (wid & 3) * 32;

    if (t < 32) ((float4*)s_bias)[t] = *(const float4*)&bias[n0 + t * 4];

    const uint32_t offA = (uint32_t)(wm0 + (lane & 15)) * ROWB
                        + (uint32_t)((lane >> 4) * 8) * 2;
    const uint32_t offB = (uint32_t)(wn0 + ((lane >> 4) & 1) * 8 + (lane & 7)) * ROWB
                        + (uint32_t)(((lane >> 3) & 1) * 8) * 2;

    float acc[4][4][4];
    #pragma unroll
    for (int i = 0; i < 4; i++)
        #pragma unroll
        for (int j = 0; j < 4; j++)
            #pragma unroll
            for (int r = 0; r < 4; r++) acc[i][j][r] = 0.0f;

    // cp.async stage of chunk c into buffer bufsel
    auto stage = [&](int c, int bufsel) {
        const int k0 = c * 32;
        const uint32_t dstb = sbase + (uint32_t)bufsel * STAGEB;
        #pragma unroll
        for (int i = 0; i < 8; i++) {
            int f   = i * 256 + t;       // 0..2047
            int p   = f >> 9;            // plane 0..3 (uniform per i)
            int cc  = f & 511;
            int row = cc >> 2;
            int qq  = cc & 3;
            uint32_t dst = dstb + (uint32_t)p * TILEB + (uint32_t)row * ROWB + (uint32_t)qq * 16;
            const __nv_bfloat16* src;
            if (p == 0)      src = Ah + (size_t)(m0 + row) * ND + k0 + qq * 8;
            else if (p == 1) src = Al + (size_t)(m0 + row) * ND + k0 + qq * 8;
            else if (p == 2) src = Wh + (size_t)(n0 + row) * ND + k0 + qq * 8;
            else             src = Wl + (size_t)(n0 + row) * ND + k0 + qq * 8;
            CP_A16(dst, src);
        }
        CP_COMMIT();
    };

    stage(0, 0);
    stage(1, 1);

    for (int c = 0; c < 32; c++) {
        if (c < 31) { CP_WAIT1(); } else { CP_WAIT0(); }
        __syncthreads();
        const uint32_t sb = sbase + (uint32_t)(c & 1) * STAGEB;

        #pragma unroll
        for (int ks = 0; ks < 2; ks++) {
            const uint32_t ka = (uint32_t)ks * 32;
            uint32_t ah[16];
            uint32_t bb[8];

            #pragma unroll
            for (int mi = 0; mi < 4; mi++)
                LDSM4(ah[mi*4+0], ah[mi*4+1], ah[mi*4+2], ah[mi*4+3],
                      sb + OFF_AHI + offA + ka + (uint32_t)mi * (16 * ROWB));
            #pragma unroll
            for (int nj = 0; nj < 2; nj++)
                LDSM4(bb[nj*4+0], bb[nj*4+1], bb[nj*4+2], bb[nj*4+3],
                      sb + OFF_WHI + offB + ka + (uint32_t)nj * (16 * ROWB));
            #pragma unroll
            for (int mi = 0; mi < 4; mi++)
                #pragma unroll
                for (int ni = 0; ni < 4; ni++)
                    MMA_BF16(acc[mi][ni], &ah[mi*4],
                             bb[(ni >> 1) * 4 + (ni & 1) * 2],
                             bb[(ni >> 1) * 4 + (ni & 1) * 2 + 1]);
            #pragma unroll
            for (int nj = 0; nj < 2; nj++)
                LDSM4(bb[nj*4+0], bb[nj*4+1], bb[nj*4+2], bb[nj*4+3],
                      sb + OFF_WLO + offB + ka + (uint32_t)nj * (16 * ROWB));
            #pragma unroll
            for (int mi = 0; mi < 4; mi++)
                #pragma unroll
                for (int ni = 0; ni < 4; ni++)
                    MMA_BF16(acc[mi][ni], &ah[mi*4],
                             bb[(ni >> 1) * 4 + (ni & 1) * 2],
                             bb[(ni >> 1) * 4 + (ni & 1) * 2 + 1]);
            #pragma unroll
            for (int mi = 0; mi < 4; mi++)
                LDSM4(ah[mi*4+0], ah[mi*4+1], ah[mi*4+2], ah[mi*4+3],
                      sb + OFF_ALO + offA + ka + (uint32_t)mi * (16 * ROWB));
            #pragma unroll
            for (int nj = 0; nj < 2; nj++)
                LDSM4(bb[nj*4+0], bb[nj*4+1], bb[nj*4+2], bb[nj*4+3],
                      sb + OFF_WHI + offB + ka + (uint32_t)nj * (16 * ROWB));
            #pragma unroll
            for (int mi = 0; mi < 4; mi++)
                #pragma unroll
                for (int ni = 0; ni < 4; ni++)
                    MMA_BF16(acc[mi][ni], &ah[mi*4],
                             bb[(ni >> 1) * 4 + (ni & 1) * 2],
                             bb[(ni >> 1) * 4 + (ni & 1) * 2 + 1]);
        }
        __syncthreads();
        if (c + 2 < 32) stage(c + 2, c & 1);
    }

    // ---- epilogue ----
    const int cr = lane >> 2;
    const int cc2 = (lane & 3) * 2;
    if (dstsel < 3) {
        const float qs = (dstsel == 0) ? QSCALE : 1.0f;
        __nv_bfloat16* Ph = (dstsel == 0) ? g_Qh : (dstsel == 1) ? g_Kh : g_Vh;
        __nv_bfloat16* Pl = (dstsel == 0) ? g_Ql : (dstsel == 1) ? g_Kl : g_Vl;
        #pragma unroll
        for (int mi = 0; mi < 4; mi++) {
            const int r0 = m0 + wm0 + mi * 16 + cr;
            #pragma unroll
            for (int ni = 0; ni < 4; ni++) {
                const int col = wn0 + ni * 8 + cc2;
                const float b0 = s_bias[col];
                const float b1 = s_bias[col + 1];
                float v0 = (acc[mi][ni][0] + b0) * qs;
                float v1 = (acc[mi][ni][1] + b1) * qs;
                float v2 = (acc[mi][ni][2] + b0) * qs;
                float v3 = (acc[mi][ni][3] + b1) * qs;
                uint32_t hi, lo;
                psplit2(v0, v1, hi, lo);
                *(uint32_t*)&Ph[(size_t)r0 * ND + n0 + col] = hi;
                *(uint32_t*)&Pl[(size_t)r0 * ND + n0 + col] = lo;
                psplit2(v2, v3, hi, lo);
                *(uint32_t*)&Ph[(size_t)(r0 + 8) * ND + n0 + col] = hi;
                *(uint32_t*)&Pl[(size_t)(r0 + 8) * ND + n0 + col] = lo;
            }
        }
    } else {
        #pragma unroll
        for (int mi = 0; mi < 4; mi++) {
            const int r0 = m0 + wm0 + mi * 16 + cr;
            #pragma unroll
            for (int ni = 0; ni < 4; ni++) {
                const int col = wn0 + ni * 8 + cc2;
                const float b0 = s_bias[col];
                const float b1 = s_bias[col + 1];
                float2 o0, o1;
                o0.x = acc[mi][ni][0] + b0;
                o0.y = acc[mi][ni][1] + b1;
                o1.x = acc[mi][ni][2] + b0;
                o1.y = acc[mi][ni][3] + b1;
                *(float2*)&Cext[(size_t)r0 * ND + n0 + col] = o0;
                *(float2*)&Cext[(size_t)(r0 + 8) * ND + n0 + col] = o1;
            }
        }
    }
}

// ============================================================================
// Tensor-core flash attention, cp.async double-buffered K/V.
// Grid (B*NH, NS/128), 256 threads (8 warps x 16 Q rows).
// Writes ctx (fp32) + merged split planes g_Mh/g_Ml.
// ============================================================================
#define AROWB 144           // 64 bf16 (128B) + 16B pad
#define KVB   36864         // one K/V buffer: 4 planes x 64 x 144
#define OKH 0
#define OKL 9216
#define OVH 18432
#define OVL 27648
#define ASMEM_TOTAL (2 * KVB)   // 73728

__global__ __launch_bounds__(256) void attn_tc(float* __restrict__ ctx_out)
{
    extern __shared__ char sm[];
    const uint32_t sb = smem_u32(sm);
    const int t = threadIdx.x, wid = t >> 5, lane = t & 31;
    const int b = blockIdx.x >> 4, h = blockIdx.x & 15;
    const int q0 = blockIdx.y * 128;

    // ---- stage Q tile (128 x 64, hi/lo) via cp.async, then load frags ----
    #pragma unroll
    for (int i = 0; i < 8; i++) {
        int f   = i * 256 + t;      // 0..2047
        int p   = f >> 10;          // 0: hi, 1: lo (uniform per i)
        int cc  = f & 1023;
        int row = cc >> 3;
        int qq  = cc & 7;
        uint32_t dst = sb + (uint32_t)p * 18432 + (uint32_t)row * AROWB + (uint32_t)qq * 16;
        const __nv_bfloat16* src = ((p == 0) ? g_Qh : g_Ql)
                                 + ((size_t)b * NS + q0 + row) * ND + h * 64 + qq * 8;
        CP_A16(dst, src);
    }
    CP_COMMIT();
    CP_WAIT0();
    __syncthreads();

    uint32_t qh[4][4], ql[4][4];
    const uint32_t offA = (uint32_t)(wid * 16 + (lane & 15)) * AROWB
                        + (uint32_t)((lane >> 4) * 8) * 2;
    #pragma unroll
    for (int ks = 0; ks < 4; ks++) {
        LDSM4(qh[ks][0], qh[ks][1], qh[ks][2], qh[ks][3], sb + offA + ks * 32);
        LDSM4(ql[ks][0], ql[ks][1], ql[ks][2], ql[ks][3], sb + 18432 + offA + ks * 32);
    }
    __syncthreads();   // Q frags in regs; buffers may be reused now

    float ctx[8][4];
    #pragma unroll
    for (int i = 0; i < 8; i++)
        #pragma unroll
        for (int j = 0; j < 4; j++) ctx[i][j] = 0.0f;
    float m0 = -1e30f, m1 = -1e30f, l0 = 0.0f, l1 = 0.0f;

    const uint32_t offBs = (uint32_t)(((lane >> 4) & 1) * 8 + (lane & 7)) * AROWB
                         + (uint32_t)(((lane >> 3) & 1) * 8) * 2;
    const uint32_t offBt = (uint32_t)(lane & 15) * AROWB + (uint32_t)((lane >> 4) * 8) * 2;

    auto stage_kv = [&](int kt, int bufsel) {
        const uint32_t dstb = sb + (uint32_t)bufsel * KVB;
        #pragma unroll
        for (int i = 0; i < 8; i++) {
            int f   = i * 256 + t;      // 0..2047
            int p   = f >> 9;           // plane 0..3 (uniform per i)
            int cc  = f & 511;
            int row = cc >> 3;
            int qq  = cc & 7;
            uint32_t dst = dstb + (uint32_t)p * 9216 + (uint32_t)row * AROWB + (uint32_t)qq * 16;
            const __nv_bfloat16* base =
                (p == 0) ? g_Kh : (p == 1) ? g_Kl : (p == 2) ? g_Vh : g_Vl;
            const __nv_bfloat16* src = base
                + ((size_t)b * NS + kt * 64 + row) * ND + h * 64 + qq * 8;
            CP_A16(dst, src);
        }
        CP_COMMIT();
    };

    stage_kv(0, 0);
    stage_kv(1, 1);

    for (int kt = 0; kt < NS / 64; kt++) {
        if (kt < 31) { CP_WAIT1(); } else { CP_WAIT0(); }
        __syncthreads();
        const uint32_t kb = sb + (uint32_t)(kt & 1) * KVB;

        // ---- scores: S = Q . K^T  (split-bf16, 3 products) ----
        float s[8][4];
        #pragma unroll
        for (int i = 0; i < 8; i++)
            #pragma unroll
            for (int j = 0; j < 4; j++) s[i][j] = 0.0f;

        #pragma unroll
        for (int ks = 0; ks < 4; ks++) {
            #pragma unroll
            for (int nbp = 0; nbp < 4; nbp++) {
                uint32_t kh[4], kl[4];
                uint32_t a = kb + (uint32_t)nbp * (16 * AROWB) + (uint32_t)ks * 32 + offBs;
                LDSM4(kh[0], kh[1], kh[2], kh[3], a + OKH);
                LDSM4(kl[0], kl[1], kl[2], kl[3], a + OKL);
                MMA_BF16(s[2*nbp],   qh[ks], kh[0], kh[1]);
                MMA_BF16(s[2*nbp+1], qh[ks], kh[2], kh[3]);
                MMA_BF16(s[2*nbp],   qh[ks], kl[0], kl[1]);
                MMA_BF16(s[2*nbp+1], qh[ks], kl[2], kl[3]);
                MMA_BF16(s[2*nbp],   ql[ks], kh[0], kh[1]);
                MMA_BF16(s[2*nbp+1], ql[ks], kh[2], kh[3]);
            }
        }

        // ---- online softmax (log2 domain) ----
        float mn0 = s[0][0], mn1 = s[0][2];
        #pragma unroll
        for (int nb = 0; nb < 8; nb++) {
            mn0 = fmaxf(mn0, fmaxf(s[nb][0], s[nb][1]));
            mn1 = fmaxf(mn1, fmaxf(s[nb][2], s[nb][3]));
        }
        mn0 = fmaxf(mn0, __shfl_xor_sync(0xffffffffu, mn0, 1));
        mn0 = fmaxf(mn0, __shfl_xor_sync(0xffffffffu, mn0, 2));
        mn1 = fmaxf(mn1, __shfl_xor_sync(0xffffffffu, mn1, 1));
        mn1 = fmaxf(mn1, __shfl_xor_sync(0xffffffffu, mn1, 2));
        float nm0 = fmaxf(m0, mn0), nm1 = fmaxf(m1, mn1);
        float c0 = ex2f(m0 - nm0), c1 = ex2f(m1 - nm1);
        m0 = nm0; m1 = nm1;

        float sum0 = 0.0f, sum1 = 0.0f;
        #pragma unroll
        for (int nb = 0; nb < 8; nb++) {
            s[nb][0] = ex2f(s[nb][0] - m0);
            s[nb][1] = ex2f(s[nb][1] - m0);
            s[nb][2] = ex2f(s[nb][2] - m1);
            s[nb][3] = ex2f(s[nb][3] - m1);
            sum0 += s[nb][0] + s[nb][1];
            sum1 += s[nb][2] + s[nb][3];
        }
        sum0 += __shfl_xor_sync(0xffffffffu, sum0, 1);
        sum0 += __shfl_xor_sync(0xffffffffu, sum0, 2);
        sum1 += __shfl_xor_sync(0xffffffffu, sum1, 1);
        sum1 += __shfl_xor_sync(0xffffffffu, sum1, 2);
        l0 = l0 * c0 + sum0;
        l1 = l1 * c1 + sum1;
        #pragma unroll
        for (int db = 0; db < 8; db++) {
            ctx[db][0] *= c0; ctx[db][1] *= c0;
            ctx[db][2] *= c1; ctx[db][3] *= c1;
        }

        // ---- P frags: C-frag -> A-frag identity, split hi/lo ----
        uint32_t pah[4][4], pal[4][4];
        #pragma unroll
        for (int ks = 0; ks < 4; ks++) {
            const int e = 2 * ks, o = 2 * ks + 1;
            psplit2(s[e][0], s[e][1], pah[ks][0], pal[ks][0]);
            psplit2(s[e][2], s[e][3], pah[ks][1], pal[ks][1]);
            psplit2(s[o][0], s[o][1], pah[ks][2], pal[ks][2]);
            psplit2(s[o][2], s[o][3], pah[ks][3], pal[ks][3]);
        }

        // ---- ctx += P . V  (split-bf16, 3 products; V via trans ldmatrix) ----
        #pragma unroll
        for (int ks = 0; ks < 4; ks++) {
            #pragma unroll
            for (int dbp = 0; dbp < 4; dbp++) {
                uint32_t vh[4], vl[4];
                uint32_t a = kb + (uint32_t)ks * (16 * AROWB) + (uint32_t)dbp * 32 + offBt;
                LDSM4T(vh[0], vh[1], vh[2], vh[3], a + OVH);
                LDSM4T(vl[0], vl[1], vl[2], vl[3], a + OVL);
                MMA_BF16(ctx[2*dbp],   pah[ks], vh[0], vh[1]);
                MMA_BF16(ctx[2*dbp+1], pah[ks], vh[2], vh[3]);
                MMA_BF16(ctx[2*dbp],   pah[ks], vl[0], vl[1]);
                MMA_BF16(ctx[2*dbp+1], pah[ks], vl[2], vl[3]);
                MMA_BF16(ctx[2*dbp],   pal[ks], vh[0], vh[1]);
                MMA_BF16(ctx[2*dbp+1], pal[ks], vh[2], vh[3]);
            }
        }
        __syncthreads();
        if (kt + 2 < NS / 64) stage_kv(kt + 2, kt & 1);
    }

    // ---- epilogue: ctx (fp32) + merged split planes ----
    const float i0 = 1.0f / l0, i1 = 1.0f / l1;
    const int r0 = q0 + wid * 16 + (lane >> 2);
    #pragma unroll
    for (int db = 0; db < 8; db++) {
        const int col = db * 8 + (lane & 3) * 2;
        float2 o0, o1;
        o0.x = ctx[db][0] * i0; o0.y = ctx[db][1] * i0;
        o1.x = ctx[db][2] * i1; o1.y = ctx[db][3] * i1;
        *(float2*)&ctx_out[(((size_t)b * NH + h) * NS + r0) * NHD + col]     = o0;
        *(float2*)&ctx_out[(((size_t)b * NH + h) * NS + r0 + 8) * NHD + col] = o1;
        uint32_t hi, lo;
        psplit2(o0.x, o0.y, hi, lo);
        *(uint32_t*)&g_Mh[((size_t)b * NS + r0) * ND + h * NHD + col] = hi;
        *(uint32_t*)&g_Ml[((size_t)b * NS + r0) * ND + h * NHD + col] = lo;
        psplit2(o1.x, o1.y, hi, lo);
        *(uint32_t*)&g_Mh[((size_t)b * NS + r0 + 8) * ND + h * NHD + col] = hi;
        *(uint32_t*)&g_Ml[((size_t)b * NS + r0 + 8) * ND + h * NHD + col] = lo;
    }
}

// ----------------------------------------------------------------------------
extern "C" void kernel_launch(void* const* d_in, const int* in_sizes, int n_in,
                              void* d_out, int out_size)
{
    (void)in_sizes; (void)n_in; (void)out_size;
    const float* q    = (const float*)d_in[0];
    const float* k    = (const float*)d_in[1];
    const float* v    = (const float*)d_in[2];
    const float* wq_w = (const float*)d_in[3];
    const float* wq_b = (const float*)d_in[4];
    const float* wk_w = (const float*)d_in[5];
    const float* wk_b = (const float*)d_in[6];
    const float* wv_w = (const float*)d_in[7];
    const float* wv_b = (const float*)d_in[8];
    const float* wo_w = (const float*)d_in[9];
    const float* wo_b = (const float*)d_in[10];

    float* out = (float*)d_out;                    // [B,S,D]
    float* ctx = out + (size_t)NM * ND;            // [B,H,S,HD]

    cudaFuncSetAttribute(gemm_tc, cudaFuncAttributeMaxDynamicSharedMemorySize,
                         GSMEM_TOTAL);
    cudaFuncSetAttribute(attn_tc, cudaFuncAttributeMaxDynamicSharedMemorySize,
                         ASMEM_TOTAL);

    // Pre-split inputs and weights into bf16 hi/lo planes.
    split_plane<<<2048, 256>>>(q, 0);
    split_plane<<<2048, 256>>>(k, 1);
    split_plane<<<2048, 256>>>(v, 2);
    split_plane<<<512, 256>>>(wq_w, 3);
    split_plane<<<512, 256>>>(wk_w, 4);
    split_plane<<<512, 256>>>(wv_w, 5);
    split_plane<<<512, 256>>>(wo_w, 6);

    dim3 gg(ND / 128, NM / 128);                   // (8, 64)

    gemm_tc<<<gg, 256, GSMEM_TOTAL>>>(wq_b, nullptr, 0, 0, 0);   // -> Q planes (scaled)
    gemm_tc<<<gg, 256, GSMEM_TOTAL>>>(wk_b, nullptr, 1, 1, 1);   // -> K planes
    gemm_tc<<<gg, 256, GSMEM_TOTAL>>>(wv_b, nullptr, 2, 2, 2);   // -> V planes

    attn_tc<<<dim3(NB * NH, NS / 128), 256, ASMEM_TOTAL>>>(ctx); // -> ctx + merged planes

    gemm_tc<<<gg, 256, GSMEM_TOTAL>>>(wo_b, out, 3, 3, 3);       // -> out
}